// round 13
// baseline (speedup 1.0000x reference)
#include <cuda_runtime.h>
#include <math.h>

#define BB 2
#define SS 2048
#define DIMD 512
#define HEADS 4
#define DH 128
#define CHUNK 16
#define NCHUNK 128
#define BH 8
#define DH2 16384
#define MAX_LR 0.01f
#define EPSV 1e-6f

// ---------------- scratch ----------------
__device__ float g_xnorm[BB*SS*DIMD];
__device__ float g_k[BH*NCHUNK*CHUNK*DH];
__device__ float g_v[BH*NCHUNK*CHUNK*DH];
__device__ float g_a[BH*NCHUNK*CHUNK*DH];    // silu(h)
__device__ float g_gn[BH*NCHUNK*CHUNK*DH];   // Gn = f*(v - pred)
__device__ float g_dh[BH*NCHUNK*CHUNK*DH];   // dh
__device__ float g_lr[BH*NCHUNK*CHUNK];
__device__ float g_mom[BH*NCHUNK];
__device__ float g_dec[BH*NCHUNK];

__device__ __forceinline__ float sigf(float x) { return 1.f / (1.f + __expf(-x)); }

// ------- packed f32x2 helpers -------
__device__ __forceinline__ unsigned long long fma2(unsigned long long a,
                                                   unsigned long long b,
                                                   unsigned long long c) {
    unsigned long long d;
    asm("fma.rn.f32x2 %0, %1, %2, %3;" : "=l"(d) : "l"(a), "l"(b), "l"(c));
    return d;
}
__device__ __forceinline__ unsigned long long dup2(float x) {
    unsigned long long d;
    unsigned int xi = __float_as_uint(x);
    asm("mov.b64 %0, {%1, %1};" : "=l"(d) : "r"(xi));
    return d;
}
__device__ __forceinline__ float2 unpk2(unsigned long long v) {
    unsigned int lo, hi;
    asm("mov.b64 {%0, %1}, %2;" : "=r"(lo), "=r"(hi) : "l"(v));
    return make_float2(__uint_as_float(lo), __uint_as_float(hi));
}
__device__ __forceinline__ void st_cs_u64(float* p, unsigned long long v) {
    asm volatile("st.global.cs.b64 [%0], %1;" :: "l"(p), "l"(v) : "memory");
}

// ---------------- K1: RMSNorm + per-token lr ----------------
__global__ void k_rmsnorm(const float* __restrict__ seq,
                          const float* __restrict__ scale,
                          const float* __restrict__ Wstep) {
    int tok = blockIdx.x;
    int tid = threadIdx.x;
    int lane = tid & 31, warp = tid >> 5;
    __shared__ float red[4];
    __shared__ float redp[4][4];

    float4 v = ((const float4*)(seq + (size_t)tok * DIMD))[tid];
    float ss = v.x*v.x + v.y*v.y + v.z*v.z + v.w*v.w;
#pragma unroll
    for (int o = 16; o; o >>= 1) ss += __shfl_xor_sync(0xffffffffu, ss, o);
    if (lane == 0) red[warp] = ss;
    __syncthreads();
    float tot = red[0] + red[1] + red[2] + red[3];
    float inv = rsqrtf(tot * (1.f / DIMD) + EPSV);

    float4 sc = ((const float4*)scale)[tid];
    float4 xn = make_float4(v.x*inv*sc.x, v.y*inv*sc.y, v.z*inv*sc.z, v.w*inv*sc.w);
    ((float4*)(g_xnorm + (size_t)tok * DIMD))[tid] = xn;

    int d0 = tid * 4;
    float4 wa = ((const float4*)Wstep)[d0 + 0];
    float4 wb = ((const float4*)Wstep)[d0 + 1];
    float4 wc = ((const float4*)Wstep)[d0 + 2];
    float4 wd = ((const float4*)Wstep)[d0 + 3];
    float p0 = xn.x*wa.x + xn.y*wb.x + xn.z*wc.x + xn.w*wd.x;
    float p1 = xn.x*wa.y + xn.y*wb.y + xn.z*wc.y + xn.w*wd.y;
    float p2 = xn.x*wa.z + xn.y*wb.z + xn.z*wc.z + xn.w*wd.z;
    float p3 = xn.x*wa.w + xn.y*wb.w + xn.z*wc.w + xn.w*wd.w;
#pragma unroll
    for (int o = 16; o; o >>= 1) {
        p0 += __shfl_xor_sync(0xffffffffu, p0, o);
        p1 += __shfl_xor_sync(0xffffffffu, p1, o);
        p2 += __shfl_xor_sync(0xffffffffu, p2, o);
        p3 += __shfl_xor_sync(0xffffffffu, p3, o);
    }
    if (lane == 0) { redp[warp][0] = p0; redp[warp][1] = p1; redp[warp][2] = p2; redp[warp][3] = p3; }
    __syncthreads();
    if (tid < 4) {
        float p = redp[0][tid] + redp[1][tid] + redp[2][tid] + redp[3][tid];
        float lrv = MAX_LR * sigf(p);
        int b = tok / SS, s = tok % SS;
        int t = s / CHUNK, c = s % CHUNK;
        g_lr[(((b * HEADS + tid) * NCHUNK + t) * CHUNK) + c] = lrv;
    }
}

// ---------------- K2: chunk means -> mom/dec ----------------
__global__ void k_chunkstats(const float* __restrict__ Wmom,
                             const float* __restrict__ Wdec) {
    int blk = blockIdx.x;
    int b = blk / NCHUNK, t = blk % NCHUNK;
    int tid = threadIdx.x;
    int lane = tid & 31, warp = tid >> 5;
    __shared__ float redp[4][8];

    int d0 = tid * 4;
    const float* xb = g_xnorm + ((size_t)(b * SS + t * CHUNK)) * DIMD;
    float4 m = make_float4(0.f, 0.f, 0.f, 0.f);
#pragma unroll
    for (int c = 0; c < CHUNK; c++) {
        float4 v = *(const float4*)(xb + (size_t)c * DIMD + d0);
        m.x += v.x; m.y += v.y; m.z += v.z; m.w += v.w;
    }
    m.x *= (1.f/CHUNK); m.y *= (1.f/CHUNK); m.z *= (1.f/CHUNK); m.w *= (1.f/CHUNK);

    float4 ma = ((const float4*)Wmom)[d0 + 0];
    float4 mb = ((const float4*)Wmom)[d0 + 1];
    float4 mc = ((const float4*)Wmom)[d0 + 2];
    float4 md = ((const float4*)Wmom)[d0 + 3];
    float4 da = ((const float4*)Wdec)[d0 + 0];
    float4 db = ((const float4*)Wdec)[d0 + 1];
    float4 dc = ((const float4*)Wdec)[d0 + 2];
    float4 dd = ((const float4*)Wdec)[d0 + 3];

    float p[8];
    p[0] = m.x*ma.x + m.y*mb.x + m.z*mc.x + m.w*md.x;
    p[1] = m.x*ma.y + m.y*mb.y + m.z*mc.y + m.w*md.y;
    p[2] = m.x*ma.z + m.y*mb.z + m.z*mc.z + m.w*md.z;
    p[3] = m.x*ma.w + m.y*mb.w + m.z*mc.w + m.w*md.w;
    p[4] = m.x*da.x + m.y*db.x + m.z*dc.x + m.w*dd.x;
    p[5] = m.x*da.y + m.y*db.y + m.z*dc.y + m.w*dd.y;
    p[6] = m.x*da.z + m.y*db.z + m.z*dc.z + m.w*dd.z;
    p[7] = m.x*da.w + m.y*db.w + m.z*dc.w + m.w*dd.w;
#pragma unroll
    for (int i = 0; i < 8; i++) {
#pragma unroll
        for (int o = 16; o; o >>= 1) p[i] += __shfl_xor_sync(0xffffffffu, p[i], o);
    }
    if (lane == 0) {
#pragma unroll
        for (int i = 0; i < 8; i++) redp[warp][i] = p[i];
    }
    __syncthreads();
    if (tid < 8) {
        float s = redp[0][tid] + redp[1][tid] + redp[2][tid] + redp[3][tid];
        float sv = sigf(s);
        int h = tid & 3;
        if (tid < 4) g_mom[(b * HEADS + h) * NCHUNK + t] = sv;
        else         g_dec[(b * HEADS + h) * NCHUNK + t] = sv;
    }
}

// ---------------- K3: kv projection (32-token tiles) ----------------
#define KV_ROWS 32
__global__ void __launch_bounds__(256, 2) k_kvproj(const float* __restrict__ Wkv) {
    extern __shared__ float xs[];   // 64 KB
    int rg  = blockIdx.x & 127;
    int cgp = blockIdx.x >> 7;
    int tid = threadIdx.x;

    const float4* src = (const float4*)(g_xnorm + (size_t)rg * KV_ROWS * DIMD);
#pragma unroll
    for (int i = tid; i < KV_ROWS * DIMD / 4; i += 256) ((float4*)xs)[i] = src[i];
    __syncthreads();

    int rs = tid >> 6;
    int cg = tid & 63;
    int r0 = rs * 8;
    int col = cgp * 256 + cg * 4;

    unsigned long long acc[8][2];
#pragma unroll
    for (int r = 0; r < 8; r++) { acc[r][0] = 0ull; acc[r][1] = 0ull; }

    const float* wbase = Wkv + col;
#pragma unroll 2
    for (int dt = 0; dt < DIMD; dt += 4) {
        float4 xv[8];
#pragma unroll
        for (int r = 0; r < 8; r++) xv[r] = *(const float4*)&xs[(r0 + r) * DIMD + dt];
#pragma unroll
        for (int dd = 0; dd < 4; dd++) {
            ulonglong2 wl = *(const ulonglong2*)(wbase + (size_t)(dt + dd) * 1024);
#pragma unroll
            for (int r = 0; r < 8; r++) {
                float xc = (dd == 0) ? xv[r].x : (dd == 1) ? xv[r].y : (dd == 2) ? xv[r].z : xv[r].w;
                unsigned long long kk = dup2(xc);
                acc[r][0] = fma2(kk, wl.x, acc[r][0]);
                acc[r][1] = fma2(kk, wl.y, acc[r][1]);
            }
        }
    }

    int isv = (col >= 512);
    int c2 = col - isv * 512;
    int h = c2 >> 7, j = c2 & 127;
    float* base = (isv ? g_v : g_k);
#pragma unroll
    for (int r = 0; r < 8; r++) {
        int tg = rg * KV_ROWS + r0 + r;
        int b = tg >> 11, s = tg & 2047;
        float* dst = base + ((size_t)((b * HEADS + h) * SS + s)) * DH + j;
        *(ulonglong2*)dst = make_ulonglong2(acc[r][0], acc[r][1]);
    }
}

// ---------------- K4a: per-chunk gradients (512 thr, 4x4 tiles) ----------------
#define CPG 4
#define MROWS 64
#define WPITCH 140

__device__ __forceinline__ void gemm64(const float* __restrict__ A,
                                       const float* __restrict__ W,
                                       int c0, int j0,
                                       unsigned long long acc[4][2]) {
#pragma unroll
    for (int i = 0; i < 4; i++) { acc[i][0] = 0ull; acc[i][1] = 0ull; }
#pragma unroll 2
    for (int dq = 0; dq < DH; dq += 4) {
        float4 ar[4];
#pragma unroll
        for (int i = 0; i < 4; i++) ar[i] = *(const float4*)&A[(c0 + i) * DH + dq];
#pragma unroll
        for (int dd = 0; dd < 4; dd++) {
            ulonglong2 w = *(const ulonglong2*)&W[(dq + dd) * WPITCH + j0];
#pragma unroll
            for (int i = 0; i < 4; i++) {
                float av = (dd == 0) ? ar[i].x : (dd == 1) ? ar[i].y : (dd == 2) ? ar[i].z : ar[i].w;
                unsigned long long aa = dup2(av);
                acc[i][0] = fma2(aa, w.x, acc[i][0]);
                acc[i][1] = fma2(aa, w.y, acc[i][1]);
            }
        }
    }
}

__global__ void __launch_bounds__(512, 1)
k_grad(const float* __restrict__ w0g_all, const float* __restrict__ w1g_all) {
    extern __shared__ float sm[];
    float* ws  = sm;
    float* ks  = ws + 128 * WPITCH;
    float* vs  = ks + MROWS * DH;
    float* as_ = vs + MROWS * DH;
    float* ss  = as_ + MROWS * DH;
    float* lrs = ss + MROWS * DH;

    int bh = blockIdx.x >> 5;
    int tg = blockIdx.x & 31;
    int t0 = tg * CPG;
    int tid = threadIdx.x;

    size_t rowbase = ((size_t)(bh * NCHUNK + t0)) * (CHUNK * DH);

    const float4* kg = (const float4*)(g_k + rowbase);
    const float4* vg = (const float4*)(g_v + rowbase);
    for (int i = tid; i < MROWS * DH / 4; i += 512) {
        ((float4*)ks)[i] = kg[i];
        ((float4*)vs)[i] = vg[i];
    }
    if (tid < MROWS) lrs[tid] = g_lr[(bh * NCHUNK + t0) * CHUNK + tid];
    const float4* w0g4 = (const float4*)(w0g_all + (size_t)bh * DH2);
    for (int i = tid; i < 4096; i += 512) {
        int row = i >> 5, col = (i & 31) * 4;
        *(float4*)&ws[row * WPITCH + col] = w0g4[i];
    }
    __syncthreads();

    int ty = tid >> 5, tx = tid & 31;
    int c0 = ty * 4, j0 = tx * 4;
    unsigned long long acc[4][2];

    // GEMM A
    gemm64(ks, ws, c0, j0, acc);
#pragma unroll
    for (int i = 0; i < 4; i++) {
        float2 h01 = unpk2(acc[i][0]), h23 = unpk2(acc[i][1]);
        float s0 = sigf(h01.x), s1 = sigf(h01.y), s2 = sigf(h23.x), s3 = sigf(h23.y);
        float4 av = make_float4(h01.x * s0, h01.y * s1, h23.x * s2, h23.y * s3);
        *(float4*)&ss[(c0 + i) * DH + j0]  = make_float4(s0, s1, s2, s3);
        *(float4*)&as_[(c0 + i) * DH + j0] = av;
        *(float4*)&g_a[rowbase + (size_t)(c0 + i) * DH + j0] = av;
    }
    __syncthreads();

    const float4* w1g4 = (const float4*)(w1g_all + (size_t)bh * DH2);
    for (int i = tid; i < 4096; i += 512) {
        int row = i >> 5, col = (i & 31) * 4;
        *(float4*)&ws[row * WPITCH + col] = w1g4[i];
    }
    __syncthreads();

    // GEMM B
    gemm64(as_, ws, c0, j0, acc);
#pragma unroll
    for (int i = 0; i < 4; i++) {
        float f = 2.f * lrs[c0 + i] * (1.f / DH);
        float2 p01 = unpk2(acc[i][0]), p23 = unpk2(acc[i][1]);
        float4 vv = *(const float4*)&vs[(c0 + i) * DH + j0];
        float4 Gn = make_float4(f * (vv.x - p01.x), f * (vv.y - p01.y),
                                f * (vv.z - p23.x), f * (vv.w - p23.y));
        *(float4*)&vs[(c0 + i) * DH + j0] = Gn;
        *(float4*)&g_gn[rowbase + (size_t)(c0 + i) * DH + j0] = Gn;
    }
    __syncthreads();

    {
        const float* w1g = w1g_all + (size_t)bh * DH2;
        for (int i = tid; i < DH2; i += 512) {
            ws[(i & 127) * WPITCH + (i >> 7)] = w1g[i];
        }
    }
    __syncthreads();

    // GEMM C
    gemm64(vs, ws, c0, j0, acc);
#pragma unroll
    for (int i = 0; i < 4; i++) {
        float2 d01 = unpk2(acc[i][0]), d23 = unpk2(acc[i][1]);
        float4 sv = *(const float4*)&ss[(c0 + i) * DH + j0];
        float4 av = *(const float4*)&as_[(c0 + i) * DH + j0];
        d01.x *= sv.x + av.x * (1.f - sv.x);
        d01.y *= sv.y + av.y * (1.f - sv.y);
        d23.x *= sv.z + av.z * (1.f - sv.z);
        d23.y *= sv.w + av.w * (1.f - sv.w);
        *(float4*)&g_dh[rowbase + (size_t)(c0 + i) * DH + j0] =
            make_float4(d01.x, d01.y, d23.x, d23.y);
    }
}

// ---------------- K4b: fused outer-product + momentum/decay scan (v5) ----------------
// grid 256: cid = blk>>4 (sel*8+bh), tile = blk&15 (4x4 of 32x32). block 256.
// Each thread: 2 rows x 2 cols. 2 t's per sync; 4-slot ring; streaming stores.
__global__ void __launch_bounds__(256) k_outer_scan(float* __restrict__ out) {
    __shared__ float As[4][CHUNK * 32];
    __shared__ float Gs[4][CHUNK * 32];
    __shared__ float moms[NCHUNK], decs[NCHUNK];

    int cid  = blockIdx.x >> 4;
    int sel  = cid >> 3, bh = cid & 7;
    int tile = blockIdx.x & 15;
    int d1b  = (tile >> 2) * 32;
    int d2b  = (tile & 3) * 32;
    int tid  = threadIdx.x;

    if (tid < NCHUNK) {
        moms[tid] = g_mom[bh * NCHUNK + tid];
        decs[tid] = 1.f - g_dec[bh * NCHUNK + tid];
    }

    const float* Asrc = sel ? g_a  : g_k;
    const float* Gsrc = sel ? g_gn : g_dh;
    size_t bhrow = (size_t)bh * (NCHUNK * CHUNK);

    // loaders: threads 0-127 stage As (16x32 = 128 float4), 128-255 stage Gs
    int isG  = (tid >= 128);
    int lt   = tid & 127;
    int ld_c = lt >> 3, ld_i = (lt & 7) * 4;
    const float* Lsrc = isG ? Gsrc : Asrc;
    float* Lbuf0 = isG ? &Gs[0][0] : &As[0][0];
    const int SLOT = CHUNK * 32;
    size_t ld_off = (size_t)(d1b * (1 - isG) + d2b * isG) + ld_i;

    // prologue: stage t=0,1 into slots 0,1
#pragma unroll
    for (int s = 0; s < 2; s++) {
        *(float4*)(Lbuf0 + s * SLOT + ld_c * 32 + ld_i) =
            *(const float4*)(Lsrc + (bhrow + (size_t)s * CHUNK + ld_c) * DH + ld_off);
    }
    __syncthreads();

    // compute mapping: 2 rows x 2 cols per thread
    int rgrp = tid >> 4;          // 0..15
    int cp   = tid & 15;          // 0..15
    int r0   = rgrp * 2;

    unsigned long long m[2], u[2];
    m[0] = m[1] = u[0] = u[1] = 0ull;

    size_t outchain = (size_t)(sel * BH + bh) * NCHUNK;

    for (int it = 0; it < NCHUNK / 2; it++) {
        int t0 = 2 * it;
        bool havenext = (it + 1 < NCHUNK / 2);
        float4 pre[2];
        if (havenext) {
#pragma unroll
            for (int s = 0; s < 2; s++) {
                pre[s] = *(const float4*)(Lsrc + (bhrow + (size_t)(t0 + 2 + s) * CHUNK + ld_c) * DH + ld_off);
            }
        }

#pragma unroll
        for (int s = 0; s < 2; s++) {
            int t = t0 + s;
            int slot = t & 3;
            unsigned long long acc0 = 0ull, acc1 = 0ull;
#pragma unroll
            for (int c = 0; c < CHUNK; c++) {
                float2 av = *(const float2*)&As[slot][c * 32 + r0];
                unsigned long long g2 = *(const unsigned long long*)&Gs[slot][c * 32 + cp * 2];
                acc0 = fma2(dup2(av.x), g2, acc0);
                acc1 = fma2(dup2(av.y), g2, acc1);
            }
            unsigned long long mo = dup2(moms[t]);
            unsigned long long de = dup2(decs[t]);
            float* op = out + (outchain + t) * DH2 + (size_t)(d1b + r0) * DH + d2b + cp * 2;
            m[0] = fma2(mo, m[0], acc0);
            u[0] = fma2(de, u[0], m[0]);
            st_cs_u64(op, u[0]);
            m[1] = fma2(mo, m[1], acc1);
            u[1] = fma2(de, u[1], m[1]);
            st_cs_u64(op + DH, u[1]);
        }

        if (havenext) {
#pragma unroll
            for (int s = 0; s < 2; s++) {
                int slot = (t0 + 2 + s) & 3;
                *(float4*)(Lbuf0 + slot * SLOT + ld_c * 32 + ld_i) = pre[s];
            }
        }
        __syncthreads();
    }
}

// ---------------- launch ----------------
extern "C" void kernel_launch(void* const* d_in, const int* in_sizes, int n_in,
                              void* d_out, int out_size) {
    const float* seq   = (const float*)d_in[0];
    const float* scale = (const float*)d_in[1];
    const float* Wkv   = (const float*)d_in[2];
    const float* Wstep = (const float*)d_in[3];
    const float* Wmom  = (const float*)d_in[4];
    const float* Wdec  = (const float*)d_in[5];
    const float* w0    = (const float*)d_in[6];
    const float* w1    = (const float*)d_in[7];
    float* out = (float*)d_out;

    const int GRAD_SMEM = (128 * WPITCH + 4 * MROWS * DH + 64) * 4;  // ~203 KB
    const int KV_SMEM = KV_ROWS * DIMD * 4;                           // 64 KB
    cudaFuncSetAttribute(k_grad, cudaFuncAttributeMaxDynamicSharedMemorySize, GRAD_SMEM);
    cudaFuncSetAttribute(k_kvproj, cudaFuncAttributeMaxDynamicSharedMemorySize, KV_SMEM);

    k_rmsnorm<<<BB * SS, 128>>>(seq, scale, Wstep);
    k_chunkstats<<<BB * NCHUNK, 128>>>(Wmom, Wdec);
    k_kvproj<<<512, 256, KV_SMEM>>>(Wkv);
    k_grad<<<BH * (NCHUNK / CPG), 512, GRAD_SMEM>>>(w0, w1);
    k_outer_scan<<<256, 256>>>(out);
}

// round 14
// speedup vs baseline: 1.0988x; 1.0988x over previous
#include <cuda_runtime.h>
#include <math.h>

#define BB 2
#define SS 2048
#define DIMD 512
#define HEADS 4
#define DH 128
#define CHUNK 16
#define NCHUNK 128
#define BH 8
#define DH2 16384
#define MAX_LR 0.01f
#define EPSV 1e-6f

// ---------------- scratch ----------------
__device__ float g_xnorm[BB*SS*DIMD];
__device__ float g_k[BH*NCHUNK*CHUNK*DH];
__device__ float g_v[BH*NCHUNK*CHUNK*DH];
__device__ float g_a[BH*NCHUNK*CHUNK*DH];    // silu(h)
__device__ float g_gn[BH*NCHUNK*CHUNK*DH];   // Gn = f*(v - pred)
__device__ float g_dh[BH*NCHUNK*CHUNK*DH];   // dh
__device__ float g_lr[BH*NCHUNK*CHUNK];
__device__ float g_mom[BH*NCHUNK];
__device__ float g_dec[BH*NCHUNK];

__device__ __forceinline__ float sigf(float x) { return 1.f / (1.f + __expf(-x)); }

// ------- packed f32x2 helpers -------
__device__ __forceinline__ unsigned long long fma2(unsigned long long a,
                                                   unsigned long long b,
                                                   unsigned long long c) {
    unsigned long long d;
    asm("fma.rn.f32x2 %0, %1, %2, %3;" : "=l"(d) : "l"(a), "l"(b), "l"(c));
    return d;
}
__device__ __forceinline__ unsigned long long dup2(float x) {
    unsigned long long d;
    unsigned int xi = __float_as_uint(x);
    asm("mov.b64 %0, {%1, %1};" : "=l"(d) : "r"(xi));
    return d;
}
__device__ __forceinline__ float2 unpk2(unsigned long long v) {
    unsigned int lo, hi;
    asm("mov.b64 {%0, %1}, %2;" : "=r"(lo), "=r"(hi) : "l"(v));
    return make_float2(__uint_as_float(lo), __uint_as_float(hi));
}
__device__ __forceinline__ void st_cs_u64(float* p, unsigned long long v) {
    asm volatile("st.global.cs.b64 [%0], %1;" :: "l"(p), "l"(v) : "memory");
}
__device__ __forceinline__ float tf32r(float x) {
    float r;
    asm("cvt.rna.tf32.f32 %0, %1;" : "=f"(r) : "f"(x));
    return r;
}
__device__ __forceinline__ void mma_tf32(float4& d,
                                         unsigned a0, unsigned a1, unsigned a2, unsigned a3,
                                         unsigned b0, unsigned b1) {
    asm("mma.sync.aligned.m16n8k8.row.col.f32.tf32.tf32.f32 "
        "{%0,%1,%2,%3}, {%4,%5,%6,%7}, {%8,%9}, {%0,%1,%2,%3};"
        : "+f"(d.x), "+f"(d.y), "+f"(d.z), "+f"(d.w)
        : "r"(a0), "r"(a1), "r"(a2), "r"(a3), "r"(b0), "r"(b1));
}

// ---------------- K1: RMSNorm + per-token lr ----------------
__global__ void k_rmsnorm(const float* __restrict__ seq,
                          const float* __restrict__ scale,
                          const float* __restrict__ Wstep) {
    int tok = blockIdx.x;
    int tid = threadIdx.x;
    int lane = tid & 31, warp = tid >> 5;
    __shared__ float red[4];
    __shared__ float redp[4][4];

    float4 v = ((const float4*)(seq + (size_t)tok * DIMD))[tid];
    float ss = v.x*v.x + v.y*v.y + v.z*v.z + v.w*v.w;
#pragma unroll
    for (int o = 16; o; o >>= 1) ss += __shfl_xor_sync(0xffffffffu, ss, o);
    if (lane == 0) red[warp] = ss;
    __syncthreads();
    float tot = red[0] + red[1] + red[2] + red[3];
    float inv = rsqrtf(tot * (1.f / DIMD) + EPSV);

    float4 sc = ((const float4*)scale)[tid];
    float4 xn = make_float4(v.x*inv*sc.x, v.y*inv*sc.y, v.z*inv*sc.z, v.w*inv*sc.w);
    ((float4*)(g_xnorm + (size_t)tok * DIMD))[tid] = xn;

    int d0 = tid * 4;
    float4 wa = ((const float4*)Wstep)[d0 + 0];
    float4 wb = ((const float4*)Wstep)[d0 + 1];
    float4 wc = ((const float4*)Wstep)[d0 + 2];
    float4 wd = ((const float4*)Wstep)[d0 + 3];
    float p0 = xn.x*wa.x + xn.y*wb.x + xn.z*wc.x + xn.w*wd.x;
    float p1 = xn.x*wa.y + xn.y*wb.y + xn.z*wc.y + xn.w*wd.y;
    float p2 = xn.x*wa.z + xn.y*wb.z + xn.z*wc.z + xn.w*wd.z;
    float p3 = xn.x*wa.w + xn.y*wb.w + xn.z*wc.w + xn.w*wd.w;
#pragma unroll
    for (int o = 16; o; o >>= 1) {
        p0 += __shfl_xor_sync(0xffffffffu, p0, o);
        p1 += __shfl_xor_sync(0xffffffffu, p1, o);
        p2 += __shfl_xor_sync(0xffffffffu, p2, o);
        p3 += __shfl_xor_sync(0xffffffffu, p3, o);
    }
    if (lane == 0) { redp[warp][0] = p0; redp[warp][1] = p1; redp[warp][2] = p2; redp[warp][3] = p3; }
    __syncthreads();
    if (tid < 4) {
        float p = redp[0][tid] + redp[1][tid] + redp[2][tid] + redp[3][tid];
        float lrv = MAX_LR * sigf(p);
        int b = tok / SS, s = tok % SS;
        int t = s / CHUNK, c = s % CHUNK;
        g_lr[(((b * HEADS + tid) * NCHUNK + t) * CHUNK) + c] = lrv;
    }
}

// ---------------- K2: chunk means -> mom/dec ----------------
__global__ void k_chunkstats(const float* __restrict__ Wmom,
                             const float* __restrict__ Wdec) {
    int blk = blockIdx.x;
    int b = blk / NCHUNK, t = blk % NCHUNK;
    int tid = threadIdx.x;
    int lane = tid & 31, warp = tid >> 5;
    __shared__ float redp[4][8];

    int d0 = tid * 4;
    const float* xb = g_xnorm + ((size_t)(b * SS + t * CHUNK)) * DIMD;
    float4 m = make_float4(0.f, 0.f, 0.f, 0.f);
#pragma unroll
    for (int c = 0; c < CHUNK; c++) {
        float4 v = *(const float4*)(xb + (size_t)c * DIMD + d0);
        m.x += v.x; m.y += v.y; m.z += v.z; m.w += v.w;
    }
    m.x *= (1.f/CHUNK); m.y *= (1.f/CHUNK); m.z *= (1.f/CHUNK); m.w *= (1.f/CHUNK);

    float4 ma = ((const float4*)Wmom)[d0 + 0];
    float4 mb = ((const float4*)Wmom)[d0 + 1];
    float4 mc = ((const float4*)Wmom)[d0 + 2];
    float4 md = ((const float4*)Wmom)[d0 + 3];
    float4 da = ((const float4*)Wdec)[d0 + 0];
    float4 db = ((const float4*)Wdec)[d0 + 1];
    float4 dc = ((const float4*)Wdec)[d0 + 2];
    float4 dd = ((const float4*)Wdec)[d0 + 3];

    float p[8];
    p[0] = m.x*ma.x + m.y*mb.x + m.z*mc.x + m.w*md.x;
    p[1] = m.x*ma.y + m.y*mb.y + m.z*mc.y + m.w*md.y;
    p[2] = m.x*ma.z + m.y*mb.z + m.z*mc.z + m.w*md.z;
    p[3] = m.x*ma.w + m.y*mb.w + m.z*mc.w + m.w*md.w;
    p[4] = m.x*da.x + m.y*db.x + m.z*dc.x + m.w*dd.x;
    p[5] = m.x*da.y + m.y*db.y + m.z*dc.y + m.w*dd.y;
    p[6] = m.x*da.z + m.y*db.z + m.z*dc.z + m.w*dd.z;
    p[7] = m.x*da.w + m.y*db.w + m.z*dc.w + m.w*dd.w;
#pragma unroll
    for (int i = 0; i < 8; i++) {
#pragma unroll
        for (int o = 16; o; o >>= 1) p[i] += __shfl_xor_sync(0xffffffffu, p[i], o);
    }
    if (lane == 0) {
#pragma unroll
        for (int i = 0; i < 8; i++) redp[warp][i] = p[i];
    }
    __syncthreads();
    if (tid < 8) {
        float s = redp[0][tid] + redp[1][tid] + redp[2][tid] + redp[3][tid];
        float sv = sigf(s);
        int h = tid & 3;
        if (tid < 4) g_mom[(b * HEADS + h) * NCHUNK + t] = sv;
        else         g_dec[(b * HEADS + h) * NCHUNK + t] = sv;
    }
}

// ---------------- K3: kv projection via tf32 tensor MMA ----------------
// grid 512: rg = blk & 127 (32-token group), cgp = blk >> 7 (256-col group).
// 256 threads = 8 warps; warp w covers cols [w*32, w*32+32) of the 256-col slab.
// xs: [32][516] tf32-rounded activations; wb: double-buffered [2][32][264] W k-tiles.
#define XP 516
#define WP 264
__global__ void __launch_bounds__(256, 1) k_kvproj(const float* __restrict__ Wkv) {
    extern __shared__ float sm2[];
    float* xs = sm2;               // 32*516 = 16512 floats
    float* wb = xs + 32 * XP;      // 2*32*264 = 16896 floats

    int rg  = blockIdx.x & 127;
    int cgp = blockIdx.x >> 7;
    int tid = threadIdx.x;
    int w = tid >> 5, lane = tid & 31;
    int g = lane >> 2, tg = lane & 3;

    // stage x (32 x 512) with tf32 rounding
    const float4* xsrc = (const float4*)(g_xnorm + (size_t)rg * 32 * DIMD);
    for (int i = tid; i < 32 * 128; i += 256) {
        int row = i >> 7, c4 = (i & 127) << 2;
        float4 v = xsrc[i];
        float* dst = xs + row * XP + c4;
        dst[0] = tf32r(v.x); dst[1] = tf32r(v.y);
        dst[2] = tf32r(v.z); dst[3] = tf32r(v.w);
    }
    // stage W k-tile 0 (rows 0..31, cols cgp*256..+256)
    const float* wsrc = Wkv + cgp * 256;
    for (int i = tid; i < 2048; i += 256) {
        int row = i >> 6, c4 = (i & 63) << 2;
        float4 v = *(const float4*)(wsrc + (size_t)row * 1024 + c4);
        float* dst = wb + row * WP + c4;
        dst[0] = tf32r(v.x); dst[1] = tf32r(v.y);
        dst[2] = tf32r(v.z); dst[3] = tf32r(v.w);
    }
    __syncthreads();

    float4 acc[2][4];
#pragma unroll
    for (int mt = 0; mt < 2; mt++)
#pragma unroll
        for (int nt = 0; nt < 4; nt++) acc[mt][nt] = make_float4(0.f, 0.f, 0.f, 0.f);

    int cw = w * 32;

    for (int kt = 0; kt < 16; kt++) {
        bool havenext = (kt + 1 < 16);
        float4 pre[8];
        if (havenext) {
#pragma unroll
            for (int s = 0; s < 8; s++) {
                int i = s * 256 + tid;
                int row = i >> 6, c4 = (i & 63) << 2;
                pre[s] = *(const float4*)(wsrc + (size_t)(kt + 1) * 32 * 1024 + (size_t)row * 1024 + c4);
            }
        }

        const float* wcur = wb + (kt & 1) * (32 * WP);
        int kb = kt * 32;
#pragma unroll
        for (int ks = 0; ks < 4; ks++) {
            int k0 = kb + ks * 8;
            unsigned a[2][4];
#pragma unroll
            for (int mt = 0; mt < 2; mt++) {
                int rb = mt * 16;
                a[mt][0] = __float_as_uint(xs[(rb + g)     * XP + k0 + tg]);
                a[mt][1] = __float_as_uint(xs[(rb + g + 8) * XP + k0 + tg]);
                a[mt][2] = __float_as_uint(xs[(rb + g)     * XP + k0 + tg + 4]);
                a[mt][3] = __float_as_uint(xs[(rb + g + 8) * XP + k0 + tg + 4]);
            }
#pragma unroll
            for (int nt = 0; nt < 4; nt++) {
                unsigned b0 = __float_as_uint(wcur[(ks * 8 + tg)     * WP + cw + nt * 8 + g]);
                unsigned b1 = __float_as_uint(wcur[(ks * 8 + tg + 4) * WP + cw + nt * 8 + g]);
                mma_tf32(acc[0][nt], a[0][0], a[0][1], a[0][2], a[0][3], b0, b1);
                mma_tf32(acc[1][nt], a[1][0], a[1][1], a[1][2], a[1][3], b0, b1);
            }
        }

        if (havenext) {
            float* dstb = wb + ((kt + 1) & 1) * (32 * WP);
#pragma unroll
            for (int s = 0; s < 8; s++) {
                int i = s * 256 + tid;
                int row = i >> 6, c4 = (i & 63) << 2;
                float* dst = dstb + row * WP + c4;
                dst[0] = tf32r(pre[s].x); dst[1] = tf32r(pre[s].y);
                dst[2] = tf32r(pre[s].z); dst[3] = tf32r(pre[s].w);
            }
        }
        __syncthreads();
    }

    // epilogue: write to g_k / g_v with head/col mapping
#pragma unroll
    for (int mt = 0; mt < 2; mt++) {
#pragma unroll
        for (int nt = 0; nt < 4; nt++) {
            int col = cgp * 256 + cw + nt * 8 + 2 * tg;
            int isv = (col >= 512);
            int c2 = col - isv * 512;
            int h = c2 >> 7, j = c2 & 127;
            float* base = (isv ? g_v : g_k);
            int tok0 = rg * 32 + mt * 16 + g;
            // rows g and g+8
            int b0i = tok0 >> 11, s0i = tok0 & 2047;
            float* d0p = base + ((size_t)((b0i * HEADS + h) * SS + s0i)) * DH + j;
            *(float2*)d0p = make_float2(acc[mt][nt].x, acc[mt][nt].y);
            int tok1 = tok0 + 8;
            int b1i = tok1 >> 11, s1i = tok1 & 2047;
            float* d1p = base + ((size_t)((b1i * HEADS + h) * SS + s1i)) * DH + j;
            *(float2*)d1p = make_float2(acc[mt][nt].z, acc[mt][nt].w);
        }
    }
}

// ---------------- K4a: per-chunk gradients (512 thr, 4x4 tiles) ----------------
#define CPG 4
#define MROWS 64
#define WPITCH 140

__device__ __forceinline__ void gemm64(const float* __restrict__ A,
                                       const float* __restrict__ W,
                                       int c0, int j0,
                                       unsigned long long acc[4][2]) {
#pragma unroll
    for (int i = 0; i < 4; i++) { acc[i][0] = 0ull; acc[i][1] = 0ull; }
#pragma unroll 2
    for (int dq = 0; dq < DH; dq += 4) {
        float4 ar[4];
#pragma unroll
        for (int i = 0; i < 4; i++) ar[i] = *(const float4*)&A[(c0 + i) * DH + dq];
#pragma unroll
        for (int dd = 0; dd < 4; dd++) {
            ulonglong2 w = *(const ulonglong2*)&W[(dq + dd) * WPITCH + j0];
#pragma unroll
            for (int i = 0; i < 4; i++) {
                float av = (dd == 0) ? ar[i].x : (dd == 1) ? ar[i].y : (dd == 2) ? ar[i].z : ar[i].w;
                unsigned long long aa = dup2(av);
                acc[i][0] = fma2(aa, w.x, acc[i][0]);
                acc[i][1] = fma2(aa, w.y, acc[i][1]);
            }
        }
    }
}

__global__ void __launch_bounds__(512, 1)
k_grad(const float* __restrict__ w0g_all, const float* __restrict__ w1g_all) {
    extern __shared__ float sm[];
    float* ws  = sm;
    float* ks  = ws + 128 * WPITCH;
    float* vs  = ks + MROWS * DH;
    float* as_ = vs + MROWS * DH;
    float* ss  = as_ + MROWS * DH;
    float* lrs = ss + MROWS * DH;

    int bh = blockIdx.x >> 5;
    int tg = blockIdx.x & 31;
    int t0 = tg * CPG;
    int tid = threadIdx.x;

    size_t rowbase = ((size_t)(bh * NCHUNK + t0)) * (CHUNK * DH);

    const float4* kg = (const float4*)(g_k + rowbase);
    const float4* vg = (const float4*)(g_v + rowbase);
    for (int i = tid; i < MROWS * DH / 4; i += 512) {
        ((float4*)ks)[i] = kg[i];
        ((float4*)vs)[i] = vg[i];
    }
    if (tid < MROWS) lrs[tid] = g_lr[(bh * NCHUNK + t0) * CHUNK + tid];
    const float4* w0g4 = (const float4*)(w0g_all + (size_t)bh * DH2);
    for (int i = tid; i < 4096; i += 512) {
        int row = i >> 5, col = (i & 31) * 4;
        *(float4*)&ws[row * WPITCH + col] = w0g4[i];
    }
    __syncthreads();

    int ty = tid >> 5, tx = tid & 31;
    int c0 = ty * 4, j0 = tx * 4;
    unsigned long long acc[4][2];

    // GEMM A
    gemm64(ks, ws, c0, j0, acc);
#pragma unroll
    for (int i = 0; i < 4; i++) {
        float2 h01 = unpk2(acc[i][0]), h23 = unpk2(acc[i][1]);
        float s0 = sigf(h01.x), s1 = sigf(h01.y), s2 = sigf(h23.x), s3 = sigf(h23.y);
        float4 av = make_float4(h01.x * s0, h01.y * s1, h23.x * s2, h23.y * s3);
        *(float4*)&ss[(c0 + i) * DH + j0]  = make_float4(s0, s1, s2, s3);
        *(float4*)&as_[(c0 + i) * DH + j0] = av;
        *(float4*)&g_a[rowbase + (size_t)(c0 + i) * DH + j0] = av;
    }
    __syncthreads();

    const float4* w1g4 = (const float4*)(w1g_all + (size_t)bh * DH2);
    for (int i = tid; i < 4096; i += 512) {
        int row = i >> 5, col = (i & 31) * 4;
        *(float4*)&ws[row * WPITCH + col] = w1g4[i];
    }
    __syncthreads();

    // GEMM B
    gemm64(as_, ws, c0, j0, acc);
#pragma unroll
    for (int i = 0; i < 4; i++) {
        float f = 2.f * lrs[c0 + i] * (1.f / DH);
        float2 p01 = unpk2(acc[i][0]), p23 = unpk2(acc[i][1]);
        float4 vv = *(const float4*)&vs[(c0 + i) * DH + j0];
        float4 Gn = make_float4(f * (vv.x - p01.x), f * (vv.y - p01.y),
                                f * (vv.z - p23.x), f * (vv.w - p23.y));
        *(float4*)&vs[(c0 + i) * DH + j0] = Gn;
        *(float4*)&g_gn[rowbase + (size_t)(c0 + i) * DH + j0] = Gn;
    }
    __syncthreads();

    {
        const float* w1g = w1g_all + (size_t)bh * DH2;
        for (int i = tid; i < DH2; i += 512) {
            ws[(i & 127) * WPITCH + (i >> 7)] = w1g[i];
        }
    }
    __syncthreads();

    // GEMM C
    gemm64(vs, ws, c0, j0, acc);
#pragma unroll
    for (int i = 0; i < 4; i++) {
        float2 d01 = unpk2(acc[i][0]), d23 = unpk2(acc[i][1]);
        float4 sv = *(const float4*)&ss[(c0 + i) * DH + j0];
        float4 av = *(const float4*)&as_[(c0 + i) * DH + j0];
        d01.x *= sv.x + av.x * (1.f - sv.x);
        d01.y *= sv.y + av.y * (1.f - sv.y);
        d23.x *= sv.z + av.z * (1.f - sv.z);
        d23.y *= sv.w + av.w * (1.f - sv.w);
        *(float4*)&g_dh[rowbase + (size_t)(c0 + i) * DH + j0] =
            make_float4(d01.x, d01.y, d23.x, d23.y);
    }
}

// ---------------- K4b: fused outer-product + momentum/decay scan (v2, best) ----------------
// grid 256: cid = blk>>4 (sel*8+bh), tile = blk&15 (4x4 of 32x32). block 128.
// 2 t's per sync; 4-slot ring buffer; streaming stores.
__global__ void __launch_bounds__(128) k_outer_scan(float* __restrict__ out) {
    __shared__ float As[4][CHUNK * 32];
    __shared__ float Gs[4][CHUNK * 32];
    __shared__ float moms[NCHUNK], decs[NCHUNK];

    int cid  = blockIdx.x >> 4;
    int sel  = cid >> 3, bh = cid & 7;
    int tile = blockIdx.x & 15;
    int d1b  = (tile >> 2) * 32;
    int d2b  = (tile & 3) * 32;
    int tid  = threadIdx.x;

    moms[tid] = g_mom[bh * NCHUNK + tid];
    decs[tid] = 1.f - g_dec[bh * NCHUNK + tid];

    const float* Asrc = sel ? g_a  : g_k;
    const float* Gsrc = sel ? g_gn : g_dh;
    size_t bhrow = (size_t)bh * (NCHUNK * CHUNK);

    int ld_c = tid >> 3, ld_i = (tid & 7) * 4;

    // prologue: stage t=0,1 into slots 0,1
#pragma unroll
    for (int s = 0; s < 2; s++) {
        *(float4*)&As[s][ld_c * 32 + ld_i] =
            *(const float4*)(Asrc + (bhrow + (size_t)s * CHUNK + ld_c) * DH + d1b + ld_i);
        *(float4*)&Gs[s][ld_c * 32 + ld_i] =
            *(const float4*)(Gsrc + (bhrow + (size_t)s * CHUNK + ld_c) * DH + d2b + ld_i);
    }
    __syncthreads();

    int w = tid >> 5, l = tid & 31;
    int rg = l >> 4, cp = l & 15;
    int r0 = w * 8 + rg * 4;

    unsigned long long m[4], u[4];
#pragma unroll
    for (int r = 0; r < 4; r++) { m[r] = 0ull; u[r] = 0ull; }

    size_t outchain = (size_t)(sel * BH + bh) * NCHUNK;

    for (int it = 0; it < NCHUNK / 2; it++) {
        int t0 = 2 * it;
        bool havenext = (it + 1 < NCHUNK / 2);
        float4 a_pre[2], g_pre[2];
        if (havenext) {
#pragma unroll
            for (int s = 0; s < 2; s++) {
                a_pre[s] = *(const float4*)(Asrc + (bhrow + (size_t)(t0 + 2 + s) * CHUNK + ld_c) * DH + d1b + ld_i);
                g_pre[s] = *(const float4*)(Gsrc + (bhrow + (size_t)(t0 + 2 + s) * CHUNK + ld_c) * DH + d2b + ld_i);
            }
        }

#pragma unroll
        for (int s = 0; s < 2; s++) {
            int t = t0 + s;
            int slot = t & 3;
            unsigned long long acc[4];
#pragma unroll
            for (int r = 0; r < 4; r++) acc[r] = 0ull;
#pragma unroll
            for (int c = 0; c < CHUNK; c++) {
                float4 av = *(const float4*)&As[slot][c * 32 + r0];
                unsigned long long g2 = *(const unsigned long long*)&Gs[slot][c * 32 + cp * 2];
                acc[0] = fma2(dup2(av.x), g2, acc[0]);
                acc[1] = fma2(dup2(av.y), g2, acc[1]);
                acc[2] = fma2(dup2(av.z), g2, acc[2]);
                acc[3] = fma2(dup2(av.w), g2, acc[3]);
            }
            unsigned long long mo = dup2(moms[t]);
            unsigned long long de = dup2(decs[t]);
            float* op = out + (outchain + t) * DH2 + (size_t)(d1b + r0) * DH + d2b + cp * 2;
#pragma unroll
            for (int r = 0; r < 4; r++) {
                m[r] = fma2(mo, m[r], acc[r]);
                u[r] = fma2(de, u[r], m[r]);
                st_cs_u64(op + (size_t)r * DH, u[r]);
            }
        }

        if (havenext) {
#pragma unroll
            for (int s = 0; s < 2; s++) {
                int slot = (t0 + 2 + s) & 3;
                *(float4*)&As[slot][ld_c * 32 + ld_i] = a_pre[s];
                *(float4*)&Gs[slot][ld_c * 32 + ld_i] = g_pre[s];
            }
        }
        __syncthreads();
    }
}

// ---------------- launch ----------------
extern "C" void kernel_launch(void* const* d_in, const int* in_sizes, int n_in,
                              void* d_out, int out_size) {
    const float* seq   = (const float*)d_in[0];
    const float* scale = (const float*)d_in[1];
    const float* Wkv   = (const float*)d_in[2];
    const float* Wstep = (const float*)d_in[3];
    const float* Wmom  = (const float*)d_in[4];
    const float* Wdec  = (const float*)d_in[5];
    const float* w0    = (const float*)d_in[6];
    const float* w1    = (const float*)d_in[7];
    float* out = (float*)d_out;

    const int GRAD_SMEM = (128 * WPITCH + 4 * MROWS * DH + 64) * 4;   // ~203 KB
    const int KV_SMEM = (32 * XP + 2 * 32 * WP) * 4;                   // 133632 B
    cudaFuncSetAttribute(k_grad, cudaFuncAttributeMaxDynamicSharedMemorySize, GRAD_SMEM);
    cudaFuncSetAttribute(k_kvproj, cudaFuncAttributeMaxDynamicSharedMemorySize, KV_SMEM);

    k_rmsnorm<<<BB * SS, 128>>>(seq, scale, Wstep);
    k_chunkstats<<<BB * NCHUNK, 128>>>(Wmom, Wdec);
    k_kvproj<<<512, 256, KV_SMEM>>>(Wkv);
    k_grad<<<BH * (NCHUNK / CPG), 512, GRAD_SMEM>>>(w0, w1);
    k_outer_scan<<<256, 128>>>(out);
}

// round 15
// speedup vs baseline: 1.2720x; 1.1576x over previous
#include <cuda_runtime.h>
#include <math.h>

#define BB 2
#define SS 2048
#define DIMD 512
#define HEADS 4
#define DH 128
#define CHUNK 16
#define NCHUNK 128
#define BH 8
#define DH2 16384
#define MAX_LR 0.01f
#define EPSV 1e-6f

// ---------------- scratch ----------------
__device__ float g_xnorm[BB*SS*DIMD];
__device__ float g_k[BH*NCHUNK*CHUNK*DH];
__device__ float g_v[BH*NCHUNK*CHUNK*DH];
__device__ float g_a[BH*NCHUNK*CHUNK*DH];    // silu(h)
__device__ float g_gn[BH*NCHUNK*CHUNK*DH];   // Gn = f*(v - pred)
__device__ float g_dh[BH*NCHUNK*CHUNK*DH];   // dh
__device__ float g_lr[BH*NCHUNK*CHUNK];
__device__ float g_mom[BH*NCHUNK];
__device__ float g_dec[BH*NCHUNK];

__device__ __forceinline__ float sigf(float x) { return 1.f / (1.f + __expf(-x)); }

// ------- packed f32x2 helpers -------
__device__ __forceinline__ unsigned long long fma2(unsigned long long a,
                                                   unsigned long long b,
                                                   unsigned long long c) {
    unsigned long long d;
    asm("fma.rn.f32x2 %0, %1, %2, %3;" : "=l"(d) : "l"(a), "l"(b), "l"(c));
    return d;
}
__device__ __forceinline__ unsigned long long dup2(float x) {
    unsigned long long d;
    unsigned int xi = __float_as_uint(x);
    asm("mov.b64 %0, {%1, %1};" : "=l"(d) : "r"(xi));
    return d;
}
__device__ __forceinline__ void st_cs_u64(float* p, unsigned long long v) {
    asm volatile("st.global.cs.b64 [%0], %1;" :: "l"(p), "l"(v) : "memory");
}
__device__ __forceinline__ float tf32r(float x) {
    float r;
    asm("cvt.rna.tf32.f32 %0, %1;" : "=f"(r) : "f"(x));
    return r;
}
__device__ __forceinline__ void mma_tf32(float4& d,
                                         unsigned a0, unsigned a1, unsigned a2, unsigned a3,
                                         unsigned b0, unsigned b1) {
    asm("mma.sync.aligned.m16n8k8.row.col.f32.tf32.tf32.f32 "
        "{%0,%1,%2,%3}, {%4,%5,%6,%7}, {%8,%9}, {%0,%1,%2,%3};"
        : "+f"(d.x), "+f"(d.y), "+f"(d.z), "+f"(d.w)
        : "r"(a0), "r"(a1), "r"(a2), "r"(a3), "r"(b0), "r"(b1));
}

// ---------------- K1: RMSNorm + per-token lr ----------------
__global__ void k_rmsnorm(const float* __restrict__ seq,
                          const float* __restrict__ scale,
                          const float* __restrict__ Wstep) {
    int tok = blockIdx.x;
    int tid = threadIdx.x;
    int lane = tid & 31, warp = tid >> 5;
    __shared__ float red[4];
    __shared__ float redp[4][4];

    float4 v = ((const float4*)(seq + (size_t)tok * DIMD))[tid];
    float ss = v.x*v.x + v.y*v.y + v.z*v.z + v.w*v.w;
#pragma unroll
    for (int o = 16; o; o >>= 1) ss += __shfl_xor_sync(0xffffffffu, ss, o);
    if (lane == 0) red[warp] = ss;
    __syncthreads();
    float tot = red[0] + red[1] + red[2] + red[3];
    float inv = rsqrtf(tot * (1.f / DIMD) + EPSV);

    float4 sc = ((const float4*)scale)[tid];
    float4 xn = make_float4(v.x*inv*sc.x, v.y*inv*sc.y, v.z*inv*sc.z, v.w*inv*sc.w);
    ((float4*)(g_xnorm + (size_t)tok * DIMD))[tid] = xn;

    int d0 = tid * 4;
    float4 wa = ((const float4*)Wstep)[d0 + 0];
    float4 wb = ((const float4*)Wstep)[d0 + 1];
    float4 wc = ((const float4*)Wstep)[d0 + 2];
    float4 wd = ((const float4*)Wstep)[d0 + 3];
    float p0 = xn.x*wa.x + xn.y*wb.x + xn.z*wc.x + xn.w*wd.x;
    float p1 = xn.x*wa.y + xn.y*wb.y + xn.z*wc.y + xn.w*wd.y;
    float p2 = xn.x*wa.z + xn.y*wb.z + xn.z*wc.z + xn.w*wd.z;
    float p3 = xn.x*wa.w + xn.y*wb.w + xn.z*wc.w + xn.w*wd.w;
#pragma unroll
    for (int o = 16; o; o >>= 1) {
        p0 += __shfl_xor_sync(0xffffffffu, p0, o);
        p1 += __shfl_xor_sync(0xffffffffu, p1, o);
        p2 += __shfl_xor_sync(0xffffffffu, p2, o);
        p3 += __shfl_xor_sync(0xffffffffu, p3, o);
    }
    if (lane == 0) { redp[warp][0] = p0; redp[warp][1] = p1; redp[warp][2] = p2; redp[warp][3] = p3; }
    __syncthreads();
    if (tid < 4) {
        float p = redp[0][tid] + redp[1][tid] + redp[2][tid] + redp[3][tid];
        float lrv = MAX_LR * sigf(p);
        int b = tok / SS, s = tok % SS;
        int t = s / CHUNK, c = s % CHUNK;
        g_lr[(((b * HEADS + tid) * NCHUNK + t) * CHUNK) + c] = lrv;
    }
}

// ---------------- K2: chunk means -> mom/dec ----------------
__global__ void k_chunkstats(const float* __restrict__ Wmom,
                             const float* __restrict__ Wdec) {
    int blk = blockIdx.x;
    int b = blk / NCHUNK, t = blk % NCHUNK;
    int tid = threadIdx.x;
    int lane = tid & 31, warp = tid >> 5;
    __shared__ float redp[4][8];

    int d0 = tid * 4;
    const float* xb = g_xnorm + ((size_t)(b * SS + t * CHUNK)) * DIMD;
    float4 m = make_float4(0.f, 0.f, 0.f, 0.f);
#pragma unroll
    for (int c = 0; c < CHUNK; c++) {
        float4 v = *(const float4*)(xb + (size_t)c * DIMD + d0);
        m.x += v.x; m.y += v.y; m.z += v.z; m.w += v.w;
    }
    m.x *= (1.f/CHUNK); m.y *= (1.f/CHUNK); m.z *= (1.f/CHUNK); m.w *= (1.f/CHUNK);

    float4 ma = ((const float4*)Wmom)[d0 + 0];
    float4 mb = ((const float4*)Wmom)[d0 + 1];
    float4 mc = ((const float4*)Wmom)[d0 + 2];
    float4 md = ((const float4*)Wmom)[d0 + 3];
    float4 da = ((const float4*)Wdec)[d0 + 0];
    float4 db = ((const float4*)Wdec)[d0 + 1];
    float4 dc = ((const float4*)Wdec)[d0 + 2];
    float4 dd = ((const float4*)Wdec)[d0 + 3];

    float p[8];
    p[0] = m.x*ma.x + m.y*mb.x + m.z*mc.x + m.w*md.x;
    p[1] = m.x*ma.y + m.y*mb.y + m.z*mc.y + m.w*md.y;
    p[2] = m.x*ma.z + m.y*mb.z + m.z*mc.z + m.w*md.z;
    p[3] = m.x*ma.w + m.y*mb.w + m.z*mc.w + m.w*md.w;
    p[4] = m.x*da.x + m.y*db.x + m.z*dc.x + m.w*dd.x;
    p[5] = m.x*da.y + m.y*db.y + m.z*dc.y + m.w*dd.y;
    p[6] = m.x*da.z + m.y*db.z + m.z*dc.z + m.w*dd.z;
    p[7] = m.x*da.w + m.y*db.w + m.z*dc.w + m.w*dd.w;
#pragma unroll
    for (int i = 0; i < 8; i++) {
#pragma unroll
        for (int o = 16; o; o >>= 1) p[i] += __shfl_xor_sync(0xffffffffu, p[i], o);
    }
    if (lane == 0) {
#pragma unroll
        for (int i = 0; i < 8; i++) redp[warp][i] = p[i];
    }
    __syncthreads();
    if (tid < 8) {
        float s = redp[0][tid] + redp[1][tid] + redp[2][tid] + redp[3][tid];
        float sv = sigf(s);
        int h = tid & 3;
        if (tid < 4) g_mom[(b * HEADS + h) * NCHUNK + t] = sv;
        else         g_dec[(b * HEADS + h) * NCHUNK + t] = sv;
    }
}

// ---------------- K3: kv projection via tf32 tensor MMA ----------------
#define XP 516
#define WP 264
__global__ void __launch_bounds__(256, 1) k_kvproj(const float* __restrict__ Wkv) {
    extern __shared__ float sm2[];
    float* xs = sm2;               // 32*516
    float* wb = xs + 32 * XP;      // 2*32*264

    int rg  = blockIdx.x & 127;
    int cgp = blockIdx.x >> 7;
    int tid = threadIdx.x;
    int w = tid >> 5, lane = tid & 31;
    int g = lane >> 2, tg = lane & 3;

    const float4* xsrc = (const float4*)(g_xnorm + (size_t)rg * 32 * DIMD);
    for (int i = tid; i < 32 * 128; i += 256) {
        int row = i >> 7, c4 = (i & 127) << 2;
        float4 v = xsrc[i];
        float* dst = xs + row * XP + c4;
        dst[0] = tf32r(v.x); dst[1] = tf32r(v.y);
        dst[2] = tf32r(v.z); dst[3] = tf32r(v.w);
    }
    const float* wsrc = Wkv + cgp * 256;
    for (int i = tid; i < 2048; i += 256) {
        int row = i >> 6, c4 = (i & 63) << 2;
        float4 v = *(const float4*)(wsrc + (size_t)row * 1024 + c4);
        float* dst = wb + row * WP + c4;
        dst[0] = tf32r(v.x); dst[1] = tf32r(v.y);
        dst[2] = tf32r(v.z); dst[3] = tf32r(v.w);
    }
    __syncthreads();

    float4 acc[2][4];
#pragma unroll
    for (int mt = 0; mt < 2; mt++)
#pragma unroll
        for (int nt = 0; nt < 4; nt++) acc[mt][nt] = make_float4(0.f, 0.f, 0.f, 0.f);

    int cw = w * 32;

    for (int kt = 0; kt < 16; kt++) {
        bool havenext = (kt + 1 < 16);
        float4 pre[8];
        if (havenext) {
#pragma unroll
            for (int s = 0; s < 8; s++) {
                int i = s * 256 + tid;
                int row = i >> 6, c4 = (i & 63) << 2;
                pre[s] = *(const float4*)(wsrc + (size_t)(kt + 1) * 32 * 1024 + (size_t)row * 1024 + c4);
            }
        }

        const float* wcur = wb + (kt & 1) * (32 * WP);
        int kb = kt * 32;
#pragma unroll
        for (int ks = 0; ks < 4; ks++) {
            int k0 = kb + ks * 8;
            unsigned a[2][4];
#pragma unroll
            for (int mt = 0; mt < 2; mt++) {
                int rb = mt * 16;
                a[mt][0] = __float_as_uint(xs[(rb + g)     * XP + k0 + tg]);
                a[mt][1] = __float_as_uint(xs[(rb + g + 8) * XP + k0 + tg]);
                a[mt][2] = __float_as_uint(xs[(rb + g)     * XP + k0 + tg + 4]);
                a[mt][3] = __float_as_uint(xs[(rb + g + 8) * XP + k0 + tg + 4]);
            }
#pragma unroll
            for (int nt = 0; nt < 4; nt++) {
                unsigned b0 = __float_as_uint(wcur[(ks * 8 + tg)     * WP + cw + nt * 8 + g]);
                unsigned b1 = __float_as_uint(wcur[(ks * 8 + tg + 4) * WP + cw + nt * 8 + g]);
                mma_tf32(acc[0][nt], a[0][0], a[0][1], a[0][2], a[0][3], b0, b1);
                mma_tf32(acc[1][nt], a[1][0], a[1][1], a[1][2], a[1][3], b0, b1);
            }
        }

        if (havenext) {
            float* dstb = wb + ((kt + 1) & 1) * (32 * WP);
#pragma unroll
            for (int s = 0; s < 8; s++) {
                int i = s * 256 + tid;
                int row = i >> 6, c4 = (i & 63) << 2;
                float* dst = dstb + row * WP + c4;
                dst[0] = tf32r(pre[s].x); dst[1] = tf32r(pre[s].y);
                dst[2] = tf32r(pre[s].z); dst[3] = tf32r(pre[s].w);
            }
        }
        __syncthreads();
    }

#pragma unroll
    for (int mt = 0; mt < 2; mt++) {
#pragma unroll
        for (int nt = 0; nt < 4; nt++) {
            int col = cgp * 256 + cw + nt * 8 + 2 * tg;
            int isv = (col >= 512);
            int c2 = col - isv * 512;
            int h = c2 >> 7, j = c2 & 127;
            float* base = (isv ? g_v : g_k);
            int tok0 = rg * 32 + mt * 16 + g;
            int b0i = tok0 >> 11, s0i = tok0 & 2047;
            float* d0p = base + ((size_t)((b0i * HEADS + h) * SS + s0i)) * DH + j;
            *(float2*)d0p = make_float2(acc[mt][nt].x, acc[mt][nt].y);
            int tok1 = tok0 + 8;
            int b1i = tok1 >> 11, s1i = tok1 & 2047;
            float* d1p = base + ((size_t)((b1i * HEADS + h) * SS + s1i)) * DH + j;
            *(float2*)d1p = make_float2(acc[mt][nt].z, acc[mt][nt].w);
        }
    }
}

// ---------------- K4a: per-chunk gradients via tf32 tensor MMA ----------------
// grid 256 (bh*32 + tg4), 512 threads = 16 warps (4m x 4n), each warp 16x32 tile.
// Pitches: activations DHP=132 (conflict-free A-frags), weights WPITCH=136 (conflict-free B-frags).
#define CPG 4
#define MROWS 64
#define WPITCH 136
#define DHP 132

__global__ void __launch_bounds__(512, 1)
k_grad(const float* __restrict__ w0g_all, const float* __restrict__ w1g_all) {
    extern __shared__ float sm[];
    float* ws  = sm;                     // 128*136
    float* ks  = ws + 128 * WPITCH;      // 64*132
    float* vs  = ks + MROWS * DHP;       // v -> Gn
    float* as_ = vs + MROWS * DHP;       // silu(h)
    float* ssb = as_ + MROWS * DHP;      // sigma(h)
    float* lrs = ssb + MROWS * DHP;      // 64

    int bh = blockIdx.x >> 5;
    int tgi = blockIdx.x & 31;
    int t0 = tgi * CPG;
    int tid = threadIdx.x;

    size_t rowbase = ((size_t)(bh * NCHUNK + t0)) * (CHUNK * DH);

    // ---- stage k, v (padded), lr, w0 (tf32) ----
    const float4* kg = (const float4*)(g_k + rowbase);
    const float4* vg = (const float4*)(g_v + rowbase);
    for (int i = tid; i < MROWS * 32; i += 512) {
        int row = i >> 5, c4 = (i & 31) << 2;
        *(float4*)&ks[row * DHP + c4] = kg[i];
        *(float4*)&vs[row * DHP + c4] = vg[i];
    }
    if (tid < MROWS) lrs[tid] = g_lr[(bh * NCHUNK + t0) * CHUNK + tid];
    const float4* w0g4 = (const float4*)(w0g_all + (size_t)bh * DH2);
    for (int i = tid; i < 4096; i += 512) {
        int row = i >> 5, col = (i & 31) << 2;
        float4 v = w0g4[i];
        float* dst = &ws[row * WPITCH + col];
        dst[0] = tf32r(v.x); dst[1] = tf32r(v.y);
        dst[2] = tf32r(v.z); dst[3] = tf32r(v.w);
    }
    __syncthreads();

    int wid = tid >> 5, lane = tid & 31;
    int g = lane >> 2, tg = lane & 3;
    int wm = wid & 3, wn = wid >> 2;
    int r0 = wm * 16, cb = wn * 32;
    int row0 = r0 + g, row1 = r0 + g + 8;

    float4 acc[4];

    // ---- GEMM A: h = k @ w0 ; sigma/silu -> ssb/as_ + g_a ----
#pragma unroll
    for (int nt = 0; nt < 4; nt++) acc[nt] = make_float4(0.f, 0.f, 0.f, 0.f);
#pragma unroll
    for (int kt = 0; kt < 16; kt++) {
        int k0 = kt * 8;
        unsigned a0 = __float_as_uint(tf32r(ks[row0 * DHP + k0 + tg]));
        unsigned a1 = __float_as_uint(tf32r(ks[row1 * DHP + k0 + tg]));
        unsigned a2 = __float_as_uint(tf32r(ks[row0 * DHP + k0 + tg + 4]));
        unsigned a3 = __float_as_uint(tf32r(ks[row1 * DHP + k0 + tg + 4]));
#pragma unroll
        for (int nt = 0; nt < 4; nt++) {
            unsigned b0 = __float_as_uint(ws[(k0 + tg)     * WPITCH + cb + nt * 8 + g]);
            unsigned b1 = __float_as_uint(ws[(k0 + tg + 4) * WPITCH + cb + nt * 8 + g]);
            mma_tf32(acc[nt], a0, a1, a2, a3, b0, b1);
        }
    }
#pragma unroll
    for (int nt = 0; nt < 4; nt++) {
        int c = cb + nt * 8 + 2 * tg;
        float s0 = sigf(acc[nt].x), s1 = sigf(acc[nt].y);
        float s2 = sigf(acc[nt].z), s3 = sigf(acc[nt].w);
        float ax = acc[nt].x * s0, ay = acc[nt].y * s1;
        float az = acc[nt].z * s2, aw = acc[nt].w * s3;
        *(float2*)&ssb[row0 * DHP + c] = make_float2(s0, s1);
        *(float2*)&ssb[row1 * DHP + c] = make_float2(s2, s3);
        *(float2*)&as_[row0 * DHP + c] = make_float2(ax, ay);
        *(float2*)&as_[row1 * DHP + c] = make_float2(az, aw);
        *(float2*)&g_a[rowbase + (size_t)row0 * DH + c] = make_float2(ax, ay);
        *(float2*)&g_a[rowbase + (size_t)row1 * DH + c] = make_float2(az, aw);
    }
    __syncthreads();

    // ---- stage w1 (tf32) ----
    const float4* w1g4 = (const float4*)(w1g_all + (size_t)bh * DH2);
    for (int i = tid; i < 4096; i += 512) {
        int row = i >> 5, col = (i & 31) << 2;
        float4 v = w1g4[i];
        float* dst = &ws[row * WPITCH + col];
        dst[0] = tf32r(v.x); dst[1] = tf32r(v.y);
        dst[2] = tf32r(v.z); dst[3] = tf32r(v.w);
    }
    __syncthreads();

    // ---- GEMM B: pred = a @ w1 ; Gn = f*(v - pred) -> vs + g_gn ----
#pragma unroll
    for (int nt = 0; nt < 4; nt++) acc[nt] = make_float4(0.f, 0.f, 0.f, 0.f);
#pragma unroll
    for (int kt = 0; kt < 16; kt++) {
        int k0 = kt * 8;
        unsigned a0 = __float_as_uint(tf32r(as_[row0 * DHP + k0 + tg]));
        unsigned a1 = __float_as_uint(tf32r(as_[row1 * DHP + k0 + tg]));
        unsigned a2 = __float_as_uint(tf32r(as_[row0 * DHP + k0 + tg + 4]));
        unsigned a3 = __float_as_uint(tf32r(as_[row1 * DHP + k0 + tg + 4]));
#pragma unroll
        for (int nt = 0; nt < 4; nt++) {
            unsigned b0 = __float_as_uint(ws[(k0 + tg)     * WPITCH + cb + nt * 8 + g]);
            unsigned b1 = __float_as_uint(ws[(k0 + tg + 4) * WPITCH + cb + nt * 8 + g]);
            mma_tf32(acc[nt], a0, a1, a2, a3, b0, b1);
        }
    }
    {
        float f0 = 2.f * lrs[row0] * (1.f / DH);
        float f1 = 2.f * lrs[row1] * (1.f / DH);
#pragma unroll
        for (int nt = 0; nt < 4; nt++) {
            int c = cb + nt * 8 + 2 * tg;
            float2 v0 = *(float2*)&vs[row0 * DHP + c];
            float2 v1 = *(float2*)&vs[row1 * DHP + c];
            float2 G0 = make_float2(f0 * (v0.x - acc[nt].x), f0 * (v0.y - acc[nt].y));
            float2 G1 = make_float2(f1 * (v1.x - acc[nt].z), f1 * (v1.y - acc[nt].w));
            *(float2*)&vs[row0 * DHP + c] = G0;
            *(float2*)&vs[row1 * DHP + c] = G1;
            *(float2*)&g_gn[rowbase + (size_t)row0 * DH + c] = G0;
            *(float2*)&g_gn[rowbase + (size_t)row1 * DH + c] = G1;
        }
    }
    __syncthreads();

    // ---- stage w1^T (tf32): ws[j][d] = w1[d][j] ----
    {
        const float* w1g = w1g_all + (size_t)bh * DH2;
        for (int i = tid; i < DH2; i += 512) {
            ws[(i & 127) * WPITCH + (i >> 7)] = tf32r(w1g[i]);
        }
    }
    __syncthreads();

    // ---- GEMM C: dA = Gn @ w1^T ; dh = dA * (s + a*(1-s)) -> g_dh ----
#pragma unroll
    for (int nt = 0; nt < 4; nt++) acc[nt] = make_float4(0.f, 0.f, 0.f, 0.f);
#pragma unroll
    for (int kt = 0; kt < 16; kt++) {
        int k0 = kt * 8;
        unsigned a0 = __float_as_uint(tf32r(vs[row0 * DHP + k0 + tg]));
        unsigned a1 = __float_as_uint(tf32r(vs[row1 * DHP + k0 + tg]));
        unsigned a2 = __float_as_uint(tf32r(vs[row0 * DHP + k0 + tg + 4]));
        unsigned a3 = __float_as_uint(tf32r(vs[row1 * DHP + k0 + tg + 4]));
#pragma unroll
        for (int nt = 0; nt < 4; nt++) {
            unsigned b0 = __float_as_uint(ws[(k0 + tg)     * WPITCH + cb + nt * 8 + g]);
            unsigned b1 = __float_as_uint(ws[(k0 + tg + 4) * WPITCH + cb + nt * 8 + g]);
            mma_tf32(acc[nt], a0, a1, a2, a3, b0, b1);
        }
    }
#pragma unroll
    for (int nt = 0; nt < 4; nt++) {
        int c = cb + nt * 8 + 2 * tg;
        float2 sv0 = *(float2*)&ssb[row0 * DHP + c];
        float2 sv1 = *(float2*)&ssb[row1 * DHP + c];
        float2 av0 = *(float2*)&as_[row0 * DHP + c];
        float2 av1 = *(float2*)&as_[row1 * DHP + c];
        float dx = acc[nt].x * (sv0.x + av0.x * (1.f - sv0.x));
        float dy = acc[nt].y * (sv0.y + av0.y * (1.f - sv0.y));
        float dz = acc[nt].z * (sv1.x + av1.x * (1.f - sv1.x));
        float dw = acc[nt].w * (sv1.y + av1.y * (1.f - sv1.y));
        *(float2*)&g_dh[rowbase + (size_t)row0 * DH + c] = make_float2(dx, dy);
        *(float2*)&g_dh[rowbase + (size_t)row1 * DH + c] = make_float2(dz, dw);
    }
}

// ---------------- K4b: fused outer-product + momentum/decay scan (v2, best) ----------------
__global__ void __launch_bounds__(128) k_outer_scan(float* __restrict__ out) {
    __shared__ float As[4][CHUNK * 32];
    __shared__ float Gs[4][CHUNK * 32];
    __shared__ float moms[NCHUNK], decs[NCHUNK];

    int cid  = blockIdx.x >> 4;
    int sel  = cid >> 3, bh = cid & 7;
    int tile = blockIdx.x & 15;
    int d1b  = (tile >> 2) * 32;
    int d2b  = (tile & 3) * 32;
    int tid  = threadIdx.x;

    moms[tid] = g_mom[bh * NCHUNK + tid];
    decs[tid] = 1.f - g_dec[bh * NCHUNK + tid];

    const float* Asrc = sel ? g_a  : g_k;
    const float* Gsrc = sel ? g_gn : g_dh;
    size_t bhrow = (size_t)bh * (NCHUNK * CHUNK);

    int ld_c = tid >> 3, ld_i = (tid & 7) * 4;

#pragma unroll
    for (int s = 0; s < 2; s++) {
        *(float4*)&As[s][ld_c * 32 + ld_i] =
            *(const float4*)(Asrc + (bhrow + (size_t)s * CHUNK + ld_c) * DH + d1b + ld_i);
        *(float4*)&Gs[s][ld_c * 32 + ld_i] =
            *(const float4*)(Gsrc + (bhrow + (size_t)s * CHUNK + ld_c) * DH + d2b + ld_i);
    }
    __syncthreads();

    int w = tid >> 5, l = tid & 31;
    int rg = l >> 4, cp = l & 15;
    int r0 = w * 8 + rg * 4;

    unsigned long long m[4], u[4];
#pragma unroll
    for (int r = 0; r < 4; r++) { m[r] = 0ull; u[r] = 0ull; }

    size_t outchain = (size_t)(sel * BH + bh) * NCHUNK;

    for (int it = 0; it < NCHUNK / 2; it++) {
        int t0 = 2 * it;
        bool havenext = (it + 1 < NCHUNK / 2);
        float4 a_pre[2], g_pre[2];
        if (havenext) {
#pragma unroll
            for (int s = 0; s < 2; s++) {
                a_pre[s] = *(const float4*)(Asrc + (bhrow + (size_t)(t0 + 2 + s) * CHUNK + ld_c) * DH + d1b + ld_i);
                g_pre[s] = *(const float4*)(Gsrc + (bhrow + (size_t)(t0 + 2 + s) * CHUNK + ld_c) * DH + d2b + ld_i);
            }
        }

#pragma unroll
        for (int s = 0; s < 2; s++) {
            int t = t0 + s;
            int slot = t & 3;
            unsigned long long acc[4];
#pragma unroll
            for (int r = 0; r < 4; r++) acc[r] = 0ull;
#pragma unroll
            for (int c = 0; c < CHUNK; c++) {
                float4 av = *(const float4*)&As[slot][c * 32 + r0];
                unsigned long long g2 = *(const unsigned long long*)&Gs[slot][c * 32 + cp * 2];
                acc[0] = fma2(dup2(av.x), g2, acc[0]);
                acc[1] = fma2(dup2(av.y), g2, acc[1]);
                acc[2] = fma2(dup2(av.z), g2, acc[2]);
                acc[3] = fma2(dup2(av.w), g2, acc[3]);
            }
            unsigned long long mo = dup2(moms[t]);
            unsigned long long de = dup2(decs[t]);
            float* op = out + (outchain + t) * DH2 + (size_t)(d1b + r0) * DH + d2b + cp * 2;
#pragma unroll
            for (int r = 0; r < 4; r++) {
                m[r] = fma2(mo, m[r], acc[r]);
                u[r] = fma2(de, u[r], m[r]);
                st_cs_u64(op + (size_t)r * DH, u[r]);
            }
        }

        if (havenext) {
#pragma unroll
            for (int s = 0; s < 2; s++) {
                int slot = (t0 + 2 + s) & 3;
                *(float4*)&As[slot][ld_c * 32 + ld_i] = a_pre[s];
                *(float4*)&Gs[slot][ld_c * 32 + ld_i] = g_pre[s];
            }
        }
        __syncthreads();
    }
}

// ---------------- launch ----------------
extern "C" void kernel_launch(void* const* d_in, const int* in_sizes, int n_in,
                              void* d_out, int out_size) {
    const float* seq   = (const float*)d_in[0];
    const float* scale = (const float*)d_in[1];
    const float* Wkv   = (const float*)d_in[2];
    const float* Wstep = (const float*)d_in[3];
    const float* Wmom  = (const float*)d_in[4];
    const float* Wdec  = (const float*)d_in[5];
    const float* w0    = (const float*)d_in[6];
    const float* w1    = (const float*)d_in[7];
    float* out = (float*)d_out;

    const int GRAD_SMEM = (128 * WPITCH + 4 * MROWS * DHP + 64) * 4;   // 205312 B
    const int KV_SMEM = (32 * XP + 2 * 32 * WP) * 4;                    // 133632 B
    cudaFuncSetAttribute(k_grad, cudaFuncAttributeMaxDynamicSharedMemorySize, GRAD_SMEM);
    cudaFuncSetAttribute(k_kvproj, cudaFuncAttributeMaxDynamicSharedMemorySize, KV_SMEM);

    k_rmsnorm<<<BB * SS, 128>>>(seq, scale, Wstep);
    k_chunkstats<<<BB * NCHUNK, 128>>>(Wmom, Wdec);
    k_kvproj<<<512, 256, KV_SMEM>>>(Wkv);
    k_grad<<<BH * (NCHUNK / CPG), 512, GRAD_SMEM>>>(w0, w1);
    k_outer_scan<<<256, 128>>>(out);
}